// round 14
// baseline (speedup 1.0000x reference)
#include <cuda_runtime.h>
#include <cuda_fp16.h>

// out[i,c] = sum_k (neigh[i,k]>=0 ? data[neigh[i,k],c] : 0) * w[k,c]
// N=200000, K=27, C=64.
// (1) convert data fp32 -> fp16 scratch with an extra all-zero row at index N;
// (2) gather: invalid neighbors redirected to the zero row AT STAGING TIME,
//     so the inner loop is one flat basic block of unconditional LDG+FMA
//     (max MLP / front-batched loads). fp32 weights, fp32 accumulate.
// 8 threads/point (16B = 8 fp16 ch each), QP=2 points/thread, TPB=128.

#define NMAX 200000
#define KK 27
#define CC 64
#define QP 2
#define TPB 128
#define PTSBLK 32      // (TPB/8)*QP ; 200000/32 = 6250 exact
#define NPAD 28

__device__ uint4 g_data16[((size_t)NMAX + 1) * 8];   // +1 zero row, 16B-aligned

__device__ __forceinline__ __half2 u2h2(unsigned u) {
    __half2 h; *reinterpret_cast<unsigned*>(&h) = u; return h;
}
__device__ __forceinline__ unsigned h22u(__half2 h) {
    unsigned u; *reinterpret_cast<__half2*>(&u) = h; return u;
}

__global__ __launch_bounds__(256)
void convert_kernel(const float4* __restrict__ src, int n8) {
    uint4* dst = g_data16;
    // zero row NMAX (deterministic every launch)
    if (blockIdx.x == 0 && threadIdx.x < 8)
        dst[(size_t)NMAX * 8 + threadIdx.x] = make_uint4(0, 0, 0, 0);
    for (int i = blockIdx.x * 256 + threadIdx.x; i < n8; i += gridDim.x * 256) {
        const float4 v0 = __ldg(src + 2 * i);
        const float4 v1 = __ldg(src + 2 * i + 1);
        uint4 o;
        o.x = h22u(__floats2half2_rn(v0.x, v0.y));
        o.y = h22u(__floats2half2_rn(v0.z, v0.w));
        o.z = h22u(__floats2half2_rn(v1.x, v1.y));
        o.w = h22u(__floats2half2_rn(v1.z, v1.w));
        dst[i] = o;
    }
}

__device__ __forceinline__ void gfma(const uint4 h, const float4 w0, const float4 w1,
                                     float4& al, float4& ah) {
    const float2 f0 = __half22float2(u2h2(h.x));
    const float2 f1 = __half22float2(u2h2(h.y));
    const float2 f2 = __half22float2(u2h2(h.z));
    const float2 f3 = __half22float2(u2h2(h.w));
    al.x = fmaf(f0.x, w0.x, al.x);  al.y = fmaf(f0.y, w0.y, al.y);
    al.z = fmaf(f1.x, w0.z, al.z);  al.w = fmaf(f1.y, w0.w, al.w);
    ah.x = fmaf(f2.x, w1.x, ah.x);  ah.y = fmaf(f2.y, w1.y, ah.y);
    ah.z = fmaf(f3.x, w1.z, ah.z);  ah.w = fmaf(f3.y, w1.w, ah.w);
}

// Fully unconditional: indices already redirected to the zero row.
#define GSTEP(K, COMP) \
    { \
        const unsigned a = (unsigned)i0.COMP, b = (unsigned)i1.COMP; \
        const uint4 ha = __ldg(dh + (size_t)a * 8 + lane); \
        const uint4 hb = __ldg(dh + (size_t)b * 8 + lane); \
        const float4 w0 = __ldg(w4g + (K) * 16 + 2 * lane); \
        const float4 w1 = __ldg(w4g + (K) * 16 + 2 * lane + 1); \
        gfma(ha, w0, w1, a0l, a0h); \
        gfma(hb, w0, w1, a1l, a1h); \
    }

__global__ __launch_bounds__(TPB)
void octree_dwconv_kernel(const float4* __restrict__ w4g,     // [27*16] float4
                          const int*    __restrict__ neigh,   // [N][27]
                          float4*       __restrict__ out)     // [N][16]
{
    __shared__ int s_n[PTSBLK * NPAD];    // 3584 B

    const int tid  = threadIdx.x;
    const int base = blockIdx.x * PTSBLK;

    // Stage indices; invalid -> zero row NMAX (select happens ONCE here)
    #pragma unroll
    for (int i = tid; i < PTSBLK * KK; i += TPB) {
        const int p = i / KK;
        const int k = i - p * KK;
        const int v = neigh[base * KK + i];
        s_n[p * NPAD + k] = (v < 0) ? NMAX : v;
    }
    __syncthreads();

    const int lane = tid & 7;        // 0..7 : 8 fp16 channels (one uint4) each
    const int g    = tid >> 3;       // group 0..15
    const int p0   = g * QP;

    const uint4* __restrict__ dh = g_data16;                 // [N+1][8] uint4
    const int4* s_n4 = reinterpret_cast<const int4*>(s_n);   // [32][7]

    float4 a0l = make_float4(0.f, 0.f, 0.f, 0.f), a0h = a0l;
    float4 a1l = a0l, a1h = a0l;

    #pragma unroll
    for (int kc = 0; kc < 7; kc++) {
        const int4 i0 = s_n4[(p0 + 0) * 7 + kc];
        const int4 i1 = s_n4[(p0 + 1) * 7 + kc];

        const int kb = kc * 4;
        GSTEP(kb + 0, x)
        GSTEP(kb + 1, y)
        GSTEP(kb + 2, z)
        if (kc < 6) {            // k = 27 doesn't exist (27 = 6*4 + 3)
            GSTEP(kb + 3, w)
        }
    }

    const unsigned ob = (unsigned)(base + p0) * 16 + 2 * lane;
    out[ob + 0]  = a0l;
    out[ob + 1]  = a0h;
    out[ob + 16] = a1l;
    out[ob + 17] = a1h;
}

extern "C" void kernel_launch(void* const* d_in, const int* in_sizes, int n_in,
                              void* d_out, int out_size) {
    const float4* data    = (const float4*)d_in[0];   // [N,64] fp32
    const float4* w4g     = (const float4*)d_in[1];   // [27,1,64] fp32
    const int*    neigh   = (const int*)d_in[2];      // [N,27] int32
    float4* out = (float4*)d_out;

    const int N  = in_sizes[0] / CC;                  // 200000
    const int n8 = in_sizes[0] / 8;                   // N*C/8 uint4

    convert_kernel<<<1184, 256>>>(data, n8);

    const int grid = (N + PTSBLK - 1) / PTSBLK;       // 6250
    octree_dwconv_kernel<<<grid, TPB>>>(w4g, neigh, out);
}

// round 15
// speedup vs baseline: 1.0976x; 1.0976x over previous
#include <cuda_runtime.h>
#include <cuda_fp16.h>

// out[i,c] = sum_k (neigh[i,k]>=0 ? data[neigh[i,k],c] : 0) * w[k,c]
// N=200000, K=27, C=64.
// HFMA2 datapath: data AND weights fp16; one hfma2 = 64 MACs/warp-instr,
// zero per-value converts in the hot loop. 32 lanes/point (half2/lane ->
// gather LDG.32 touches exactly ONE 128B line), QP=4 points/warp.
// fp16 accumulation chunked 7/7/7/6 with fp32 flush for precision.
// Invalid neighbors redirected to zero row N at staging time (branchless).

#define NMAX 200000
#define KK 27
#define QP 4
#define TPB 128
#define PTSBLK 16      // 4 warps * QP ; 200000/16 = 12500 exact

__device__ unsigned g_data16[((size_t)NMAX + 1) * 32];   // [N+1][32] half2 rows
__device__ unsigned g_w16[KK * 32];                      // [27][32] half2

__device__ __forceinline__ __half2 u2h2(unsigned u) {
    __half2 h; *reinterpret_cast<unsigned*>(&h) = u; return h;
}
__device__ __forceinline__ unsigned h22u(__half2 h) {
    unsigned u; *reinterpret_cast<__half2*>(&u) = h; return u;
}

__global__ __launch_bounds__(256)
void convert_kernel(const float2* __restrict__ src,   // data as float2 pairs
                    const float2* __restrict__ wsrc,  // weights as float2 pairs
                    int n2)                           // N*C/2
{
    if (blockIdx.x == 0) {
        // weights: 27*32 = 864 half2
        for (int j = threadIdx.x; j < KK * 32; j += 256)
            g_w16[j] = h22u(__float22half2_rn(__ldg(wsrc + j)));
        // zero row at index NMAX
        if (threadIdx.x < 32)
            g_data16[(size_t)NMAX * 32 + threadIdx.x] = 0u;
    }
    for (int i = blockIdx.x * 256 + threadIdx.x; i < n2; i += gridDim.x * 256)
        g_data16[i] = h22u(__float22half2_rn(__ldg(src + i)));
}

#define KSTEP(K) \
    { \
        const int4 ip = st4[(K) * 4 + w]; \
        const __half2 wv = u2h2(__ldg(g_w16 + (K) * 32 + c)); \
        a0 = __hfma2(u2h2(__ldg(dh + (unsigned)ip.x * 32 + c)), wv, a0); \
        a1 = __hfma2(u2h2(__ldg(dh + (unsigned)ip.y * 32 + c)), wv, a1); \
        a2 = __hfma2(u2h2(__ldg(dh + (unsigned)ip.z * 32 + c)), wv, a2); \
        a3 = __hfma2(u2h2(__ldg(dh + (unsigned)ip.w * 32 + c)), wv, a3); \
    }

#define FLUSH1(A, F) \
    { const float2 t = __half22float2(A); F.x += t.x; F.y += t.y; A = u2h2(0u); }

#define FLUSH \
    FLUSH1(a0, f0) FLUSH1(a1, f1) FLUSH1(a2, f2) FLUSH1(a3, f3)

__global__ __launch_bounds__(TPB)
void octree_dwconv_kernel(const int*  __restrict__ neigh,   // [N][27]
                          float2*     __restrict__ out)     // [N][32] float2
{
    __shared__ int s_t[KK * PTSBLK];   // transposed [27][16]

    const int tid  = threadIdx.x;
    const int base = blockIdx.x * PTSBLK;

    // Stage indices transposed; invalid -> zero row NMAX
    #pragma unroll
    for (int i = tid; i < PTSBLK * KK; i += TPB) {
        const int p = i / KK;
        const int k = i - p * KK;
        const int v = neigh[base * KK + i];
        s_t[k * PTSBLK + p] = (v < 0) ? NMAX : v;
    }
    __syncthreads();

    const int c = tid & 31;          // lane = channel pair (half2)
    const int w = tid >> 5;          // warp = 4 consecutive points

    const int4* st4 = reinterpret_cast<const int4*>(s_t);   // [27][4]
    const unsigned* __restrict__ dh = g_data16;

    __half2 a0 = u2h2(0u), a1 = a0, a2 = a0, a3 = a0;
    float2 f0 = make_float2(0.f, 0.f), f1 = f0, f2 = f0, f3 = f0;

    #pragma unroll
    for (int k = 0; k < KK; k++) {
        KSTEP(k)
        if (k == 6 || k == 13 || k == 20 || k == KK - 1) { FLUSH }
    }

    const unsigned row = (unsigned)(base + w * QP);
    out[(row + 0) * 32 + c] = f0;
    out[(row + 1) * 32 + c] = f1;
    out[(row + 2) * 32 + c] = f2;
    out[(row + 3) * 32 + c] = f3;
}

extern "C" void kernel_launch(void* const* d_in, const int* in_sizes, int n_in,
                              void* d_out, int out_size) {
    const float2* data    = (const float2*)d_in[0];   // [N,64] fp32
    const float2* wsrc    = (const float2*)d_in[1];   // [27,1,64] fp32
    const int*    neigh   = (const int*)d_in[2];      // [N,27] int32
    float2* out = (float2*)d_out;

    const int n2 = in_sizes[0] / 2;                   // N*C/2 half2 outputs

    convert_kernel<<<1184, 256>>>(data, wsrc, n2);

    const int N = in_sizes[0] / 64;                   // 200000
    const int grid = (N + PTSBLK - 1) / PTSBLK;       // 12500
    octree_dwconv_kernel<<<grid, TPB>>>(neigh, out);
}

// round 16
// speedup vs baseline: 1.2789x; 1.1652x over previous
#include <cuda_runtime.h>
#include <cuda_fp16.h>

// out[i,c] = sum_k (neigh[i,k]>=0 ? data[neigh[i,k],c] : 0) * w[k,c]
// N=200000, K=27, C=64.
// HFMA2 datapath: data + weights fp16 (one hfma2 = 64 MACs/warp-instr).
// 32 lanes/point (half2/lane -> gather LDG.32 = one 128B line), QP=4/warp.
// fp16 accum chunked 7/7/7/6 with fp32 flushes. Invalid -> zero row N,
// indices PRE-SCALED by 32 at staging (kills one IMAD per gather).
// Convert prologue vectorized: 2x float4 load -> 1x uint4 store.

#define NMAX 200000
#define KK 27
#define QP 4
#define TPB 128
#define PTSBLK 16      // 4 warps * QP ; 200000/16 = 12500 exact

__device__ unsigned g_data16[((size_t)NMAX + 1) * 32];   // [N+1][32] half2 rows
__device__ unsigned g_w16[KK * 32];                      // [27][32] half2

__device__ __forceinline__ __half2 u2h2(unsigned u) {
    __half2 h; *reinterpret_cast<unsigned*>(&h) = u; return h;
}
__device__ __forceinline__ unsigned h22u(__half2 h) {
    unsigned u; *reinterpret_cast<__half2*>(&u) = h; return u;
}

__global__ __launch_bounds__(256)
void convert_kernel(const float4* __restrict__ src,   // data as float4
                    const float2* __restrict__ wsrc,  // weights as float2
                    int n8)                           // N*C/8 uint4 outputs
{
    if (blockIdx.x == 0) {
        for (int j = threadIdx.x; j < KK * 32; j += 256)
            g_w16[j] = h22u(__float22half2_rn(__ldg(wsrc + j)));
        if (threadIdx.x < 8)
            reinterpret_cast<uint4*>(g_data16)[(size_t)NMAX * 8 + threadIdx.x] =
                make_uint4(0, 0, 0, 0);
    }
    uint4* dst = reinterpret_cast<uint4*>(g_data16);
    for (int i = blockIdx.x * 256 + threadIdx.x; i < n8; i += gridDim.x * 256) {
        const float4 v0 = __ldg(src + 2 * i);
        const float4 v1 = __ldg(src + 2 * i + 1);
        uint4 o;
        o.x = h22u(__floats2half2_rn(v0.x, v0.y));
        o.y = h22u(__floats2half2_rn(v0.z, v0.w));
        o.z = h22u(__floats2half2_rn(v1.x, v1.y));
        o.w = h22u(__floats2half2_rn(v1.z, v1.w));
        dst[i] = o;
    }
}

#define KSTEP(K) \
    { \
        const int4 ip = st4[(K) * 4 + w]; \
        const __half2 wv = u2h2(__ldg(wc + (K) * 32)); \
        a0 = __hfma2(u2h2(__ldg(dhc + (unsigned)ip.x)), wv, a0); \
        a1 = __hfma2(u2h2(__ldg(dhc + (unsigned)ip.y)), wv, a1); \
        a2 = __hfma2(u2h2(__ldg(dhc + (unsigned)ip.z)), wv, a2); \
        a3 = __hfma2(u2h2(__ldg(dhc + (unsigned)ip.w)), wv, a3); \
    }

#define FLUSH1(A, F) \
    { const float2 t = __half22float2(A); F.x += t.x; F.y += t.y; A = u2h2(0u); }

#define FLUSH \
    FLUSH1(a0, f0) FLUSH1(a1, f1) FLUSH1(a2, f2) FLUSH1(a3, f3)

__global__ __launch_bounds__(TPB)
void octree_dwconv_kernel(const int*  __restrict__ neigh,   // [N][27]
                          float2*     __restrict__ out)     // [N][32] float2
{
    __shared__ int s_t[KK * PTSBLK];   // transposed [27][16], PRE-SCALED by 32

    const int tid  = threadIdx.x;
    const int base = blockIdx.x * PTSBLK;

    #pragma unroll
    for (int i = tid; i < PTSBLK * KK; i += TPB) {
        const int p = i / KK;
        const int k = i - p * KK;
        const int v = neigh[base * KK + i];
        s_t[k * PTSBLK + p] = ((v < 0) ? NMAX : v) * 32;   // pre-scaled row offset
    }
    __syncthreads();

    const int c = tid & 31;          // lane = channel pair (half2)
    const int w = tid >> 5;          // warp = 4 consecutive points

    const int4* st4 = reinterpret_cast<const int4*>(s_t);   // [27][4]
    const unsigned* __restrict__ dhc = g_data16 + c;        // lane-anchored
    const unsigned* __restrict__ wc  = g_w16 + c;

    __half2 a0 = u2h2(0u), a1 = a0, a2 = a0, a3 = a0;
    float2 f0 = make_float2(0.f, 0.f), f1 = f0, f2 = f0, f3 = f0;

    #pragma unroll
    for (int k = 0; k < KK; k++) {
        KSTEP(k)
        if (k == 6 || k == 13 || k == 20 || k == KK - 1) { FLUSH }
    }

    const unsigned row = (unsigned)(base + w * QP);
    out[(row + 0) * 32 + c] = f0;
    out[(row + 1) * 32 + c] = f1;
    out[(row + 2) * 32 + c] = f2;
    out[(row + 3) * 32 + c] = f3;
}

extern "C" void kernel_launch(void* const* d_in, const int* in_sizes, int n_in,
                              void* d_out, int out_size) {
    const float4* data    = (const float4*)d_in[0];   // [N,64] fp32
    const float2* wsrc    = (const float2*)d_in[1];   // [27,1,64] fp32
    const int*    neigh   = (const int*)d_in[2];      // [N,27] int32
    float2* out = (float2*)d_out;

    const int n8 = in_sizes[0] / 8;                   // N*C/8 uint4

    convert_kernel<<<1184, 256>>>(data, wsrc, n8);

    const int N = in_sizes[0] / 64;                   // 200000
    const int grid = (N + PTSBLK - 1) / PTSBLK;       // 12500
    octree_dwconv_kernel<<<grid, TPB>>>(neigh, out);
}

// round 17
// speedup vs baseline: 1.3308x; 1.0406x over previous
#include <cuda_runtime.h>
#include <cuda_fp16.h>

// out[i,c] = sum_k (neigh[i,k]>=0 ? data[neigh[i,k],c] : 0) * w[k,c]
// N=200000, K=27, C=64.
// HFMA2 datapath: data + weights fp16. 32 lanes/point (half2/lane ->
// gather LDG.32 = one 128B line), QP=4 points/warp.
// WEIGHTS IN SMEM: per-k weight read is an LDS (separate smem crossbar),
// offloading ~20% of the contended L1tex wavefronts. Conflict-free stride-1.
// fp16 accum chunked 7/7/7/6 with fp32 flushes. Invalid -> zero row N,
// indices pre-scaled by 32 at staging. Convert prologue unrolled x2.

#define NMAX 200000
#define KK 27
#define QP 4
#define TPB 128
#define PTSBLK 16      // 4 warps * QP ; 200000/16 = 12500 exact

__device__ unsigned g_data16[((size_t)NMAX + 1) * 32];   // [N+1][32] half2 rows
__device__ unsigned g_w16[KK * 32];                      // [27][32] half2

__device__ __forceinline__ __half2 u2h2(unsigned u) {
    __half2 h; *reinterpret_cast<unsigned*>(&h) = u; return h;
}
__device__ __forceinline__ unsigned h22u(__half2 h) {
    unsigned u; *reinterpret_cast<__half2*>(&u) = h; return u;
}

__global__ __launch_bounds__(256)
void convert_kernel(const float4* __restrict__ src,   // data as float4
                    const float2* __restrict__ wsrc,  // weights as float2
                    int n8)                           // N*C/8 uint4 outputs
{
    if (blockIdx.x == 0) {
        for (int j = threadIdx.x; j < KK * 32; j += 256)
            g_w16[j] = h22u(__float22half2_rn(__ldg(wsrc + j)));
        if (threadIdx.x < 8)
            reinterpret_cast<uint4*>(g_data16)[(size_t)NMAX * 8 + threadIdx.x] =
                make_uint4(0, 0, 0, 0);
    }
    uint4* dst = reinterpret_cast<uint4*>(g_data16);
    const int stride = gridDim.x * 256;
    int i = blockIdx.x * 256 + threadIdx.x;
    // unrolled x2: two independent uint4 outputs in flight
    for (; i + stride < n8; i += 2 * stride) {
        const int j = i + stride;
        const float4 a0 = __ldg(src + 2 * i);
        const float4 a1 = __ldg(src + 2 * i + 1);
        const float4 b0 = __ldg(src + 2 * j);
        const float4 b1 = __ldg(src + 2 * j + 1);
        uint4 oa, ob;
        oa.x = h22u(__floats2half2_rn(a0.x, a0.y));
        oa.y = h22u(__floats2half2_rn(a0.z, a0.w));
        oa.z = h22u(__floats2half2_rn(a1.x, a1.y));
        oa.w = h22u(__floats2half2_rn(a1.z, a1.w));
        ob.x = h22u(__floats2half2_rn(b0.x, b0.y));
        ob.y = h22u(__floats2half2_rn(b0.z, b0.w));
        ob.z = h22u(__floats2half2_rn(b1.x, b1.y));
        ob.w = h22u(__floats2half2_rn(b1.z, b1.w));
        dst[i] = oa;
        dst[j] = ob;
    }
    for (; i < n8; i += stride) {
        const float4 v0 = __ldg(src + 2 * i);
        const float4 v1 = __ldg(src + 2 * i + 1);
        uint4 o;
        o.x = h22u(__floats2half2_rn(v0.x, v0.y));
        o.y = h22u(__floats2half2_rn(v0.z, v0.w));
        o.z = h22u(__floats2half2_rn(v1.x, v1.y));
        o.w = h22u(__floats2half2_rn(v1.z, v1.w));
        dst[i] = o;
    }
}

#define KSTEP(K) \
    { \
        const int4 ip = st4[(K) * 4 + w]; \
        const __half2 wv = u2h2(s_w[(K) * 32 + c]); \
        a0 = __hfma2(u2h2(__ldg(dhc + (unsigned)ip.x)), wv, a0); \
        a1 = __hfma2(u2h2(__ldg(dhc + (unsigned)ip.y)), wv, a1); \
        a2 = __hfma2(u2h2(__ldg(dhc + (unsigned)ip.z)), wv, a2); \
        a3 = __hfma2(u2h2(__ldg(dhc + (unsigned)ip.w)), wv, a3); \
    }

#define FLUSH1(A, F) \
    { const float2 t = __half22float2(A); F.x += t.x; F.y += t.y; A = u2h2(0u); }

#define FLUSH \
    FLUSH1(a0, f0) FLUSH1(a1, f1) FLUSH1(a2, f2) FLUSH1(a3, f3)

__global__ __launch_bounds__(TPB)
void octree_dwconv_kernel(const int*  __restrict__ neigh,   // [N][27]
                          float2*     __restrict__ out)     // [N][32] float2
{
    __shared__ int      s_t[KK * PTSBLK];   // transposed [27][16], pre-scaled by 32
    __shared__ unsigned s_w[KK * 32];       // [27][32] half2 weights, 3456 B

    const int tid  = threadIdx.x;
    const int base = blockIdx.x * PTSBLK;

    // Stage weights into smem (uint4 vector copies: 216 uint4)
    {
        const uint4* wg = reinterpret_cast<const uint4*>(g_w16);
        uint4* ws = reinterpret_cast<uint4*>(s_w);
        #pragma unroll
        for (int i = tid; i < KK * 32 / 4; i += TPB)
            ws[i] = wg[i];
    }
    // Stage indices transposed; invalid -> zero row NMAX; pre-scale by 32
    #pragma unroll
    for (int i = tid; i < PTSBLK * KK; i += TPB) {
        const int p = i / KK;
        const int k = i - p * KK;
        const int v = neigh[base * KK + i];
        s_t[k * PTSBLK + p] = ((v < 0) ? NMAX : v) * 32;
    }
    __syncthreads();

    const int c = tid & 31;          // lane = channel pair (half2)
    const int w = tid >> 5;          // warp = 4 consecutive points

    const int4* st4 = reinterpret_cast<const int4*>(s_t);   // [27][4]
    const unsigned* __restrict__ dhc = g_data16 + c;        // lane-anchored

    __half2 a0 = u2h2(0u), a1 = a0, a2 = a0, a3 = a0;
    float2 f0 = make_float2(0.f, 0.f), f1 = f0, f2 = f0, f3 = f0;

    #pragma unroll
    for (int k = 0; k < KK; k++) {
        KSTEP(k)
        if (k == 6 || k == 13 || k == 20 || k == KK - 1) { FLUSH }
    }

    const unsigned row = (unsigned)(base + w * QP);
    out[(row + 0) * 32 + c] = f0;
    out[(row + 1) * 32 + c] = f1;
    out[(row + 2) * 32 + c] = f2;
    out[(row + 3) * 32 + c] = f3;
}

extern "C" void kernel_launch(void* const* d_in, const int* in_sizes, int n_in,
                              void* d_out, int out_size) {
    const float4* data    = (const float4*)d_in[0];   // [N,64] fp32
    const float2* wsrc    = (const float2*)d_in[1];   // [27,1,64] fp32
    const int*    neigh   = (const int*)d_in[2];      // [N,27] int32
    float2* out = (float2*)d_out;

    const int n8 = in_sizes[0] / 8;                   // N*C/8 uint4

    convert_kernel<<<1184, 256>>>(data, wsrc, n8);

    const int N = in_sizes[0] / 64;                   // 200000
    const int grid = (N + PTSBLK - 1) / PTSBLK;       // 12500
    octree_dwconv_kernel<<<grid, TPB>>>(neigh, out);
}